// round 15
// baseline (speedup 1.0000x reference)
#include <cuda_runtime.h>
#include <cuda_fp16.h>
#include <cstdint>

#define D_MODEL 1024
#define NH 16
#define DK 64
#define BATCH 2
#define SEQ 2048
#define ROWS (BATCH*SEQ)

// Q prescale: (1/sqrt(64)) * log2(e)
#define QSCALE 0.18033688011112042f

// ---- scratch (no allocations allowed) ----
__device__ __align__(16) __half g_xt [ROWS * 1024];
__device__ __align__(16) __half g_wqt[1024 * 1024];
__device__ __align__(16) __half g_wkt[256  * 1024];
__device__ __align__(16) __half g_wvt[256  * 1024];
__device__ __align__(16) __half g_wot[1024 * 1024];
__device__ __align__(16) __half g_q  [ROWS * 1024];
__device__ __align__(16) __half g_k  [ROWS * 256];
__device__ __align__(16) __half g_vt [256  * ROWS];
__device__ __align__(16) __half g_o  [ROWS * 1024];

// fp16 pair permutation within a 64-feature block:
// feature k = 16*kk + 8*h2 + 2*tg + s  <->  stored pos j = 16*tg + 4*kk + 2*h2 + s
__device__ __forceinline__ int j16h(int k) {
    return ((k >> 1) & 3) * 16 + (k >> 4) * 4 + ((k >> 3) & 1) * 2 + (k & 1);
}
__device__ __forceinline__ int sig64h(int j) {
    return ((j >> 2) & 3) * 16 + ((j >> 1) & 1) * 8 + (j >> 4) * 2 + (j & 1);
}

__device__ __forceinline__ uint32_t packh2(float lo, float hi) {
    __half2 h = __floats2half2_rn(lo, hi);   // single cvt.rn.f16x2.f32
    return *reinterpret_cast<uint32_t*>(&h);
}
__device__ __forceinline__ uint32_t ex2h2(uint32_t x) {
    uint32_t y;
    asm("ex2.approx.f16x2 %0, %1;" : "=r"(y) : "r"(x));
    return y;
}

__device__ __forceinline__ void mma16(float* c, const uint32_t* a, const uint32_t* b) {
    asm volatile(
        "mma.sync.aligned.m16n8k16.row.col.f32.f16.f16.f32 "
        "{%0,%1,%2,%3},{%4,%5,%6,%7},{%8,%9},{%0,%1,%2,%3};"
        : "+f"(c[0]), "+f"(c[1]), "+f"(c[2]), "+f"(c[3])
        : "r"(a[0]), "r"(a[1]), "r"(a[2]), "r"(a[3]), "r"(b[0]), "r"(b[1]));
}

__device__ __forceinline__ void cpa16(uint32_t dst, const void* src) {
    asm volatile("cp.async.cg.shared.global [%0], [%1], 16;\n" :: "r"(dst), "l"(src) : "memory");
}
#define CP_COMMIT asm volatile("cp.async.commit_group;\n" ::: "memory")
#define CP_WAIT1  asm volatile("cp.async.wait_group 1;\n" ::: "memory")
#define CP_WAIT0  asm volatile("cp.async.wait_group 0;\n" ::: "memory")

#define HP 36   // smem pitch in words for a 64-half (128B) row

// ============================================================
// Prepass kernels
// ============================================================
__global__ __launch_bounds__(256) void prep_act(const float* __restrict__ in) {
    int i4 = (blockIdx.x * 256 + threadIdx.x) * 4;
    int base = i4 & ~63;
    float f0 = in[base + sig64h((i4 + 0) & 63)];
    float f1 = in[base + sig64h((i4 + 1) & 63)];
    float f2 = in[base + sig64h((i4 + 2) & 63)];
    float f3 = in[base + sig64h((i4 + 3) & 63)];
    __half2* o2 = (__half2*)(g_xt + i4);
    o2[0] = __floats2half2_rn(f0, f1);
    o2[1] = __floats2half2_rn(f2, f3);
}

__global__ __launch_bounds__(256) void prep_w(
    const float* __restrict__ Wq, const float* __restrict__ Wk,
    const float* __restrict__ Wv, const float* __restrict__ Wo)
{
    int col = blockIdx.x * 256 + threadIdx.x;
    int kp = blockIdx.y;
    int k = (kp & ~63) + sig64h(kp & 63);
    const float* W; __half* Wt; int N, n;
    if (col < 1024)      { W = Wq; Wt = g_wqt; N = 1024; n = col; }
    else if (col < 1280) { W = Wk; Wt = g_wkt; N = 256;  n = col - 1024; }
    else if (col < 1536) { W = Wv; Wt = g_wvt; N = 256;  n = col - 1280; }
    else                 { W = Wo; Wt = g_wot; N = 1024; n = col - 1536; }
    Wt[(size_t)n * 1024 + kp] = __float2half_rn(W[(size_t)k * N + n]);
}

// ============================================================
// fp16 GEMM: C[M,N] = A[M,1024] @ Bt[N,1024]^T + bias
// block 128x128, 8 warps (2x4) of 64x32, BK=64 (4 x k16 mma),
// cp.async double buffer (72KB).
// ============================================================
#define GSTGH (256 * HP)

__device__ __forceinline__ void cp_stage_gemm(uint32_t sb, const __half* Ap, const __half* Bp, int tid) {
#pragma unroll
    for (int t = 0; t < 4; t++) {
        int cid = tid + t * 256; int row = cid >> 3, ch = cid & 7;
        cpa16(sb + (uint32_t)(row * HP + ch * 4) * 4, Ap + (size_t)row * 1024 + ch * 8);
    }
#pragma unroll
    for (int t = 0; t < 4; t++) {
        int cid = tid + t * 256; int row = cid >> 3, ch = cid & 7;
        cpa16(sb + (uint32_t)((128 + row) * HP + ch * 4) * 4, Bp + (size_t)row * 1024 + ch * 8);
    }
    CP_COMMIT;
}

template<int EPI>
__device__ __forceinline__ void gemm_body(
    const __half* __restrict__ A, const __half* __restrict__ Bt,
    const float* __restrict__ bias, void* __restrict__ Cv,
    int N, int bm, int bn)
{
    extern __shared__ uint32_t smg[];
    const int tid = threadIdx.x, lane = tid & 31, w = tid >> 5;
    const int g = lane >> 2, tg = lane & 3;
    const int wm = (w >> 2) * 64, wn = (w & 3) * 32;
    uint32_t sbase = (uint32_t)__cvta_generic_to_shared(smg);
    const __half* Ab = A + (size_t)bm * 1024;
    const __half* Bb = Bt + (size_t)bn * 1024;

    float acc[4][4][4];
#pragma unroll
    for (int i = 0; i < 4; i++)
#pragma unroll
        for (int j = 0; j < 4; j++)
#pragma unroll
            for (int q = 0; q < 4; q++) acc[i][j][q] = 0.f;

    cp_stage_gemm(sbase, Ab, Bb, tid);
    for (int kt = 0; kt < 16; kt++) {
        if (kt < 15) {
            cp_stage_gemm(sbase + (uint32_t)(((kt + 1) & 1) * GSTGH * 4),
                          Ab + (kt + 1) * 64, Bb + (kt + 1) * 64, tid);
            CP_WAIT1;
        } else {
            CP_WAIT0;
        }
        __syncthreads();
        const uint32_t* Ss = smg + (kt & 1) * GSTGH;

        uint4 b4[4][2];
#pragma unroll
        for (int nf = 0; nf < 4; nf++) {
            const uint4* p = (const uint4*)(Ss + (128 + wn + nf * 8 + g) * HP + tg * 8);
            b4[nf][0] = p[0]; b4[nf][1] = p[1];
        }
#pragma unroll
        for (int mf = 0; mf < 4; mf++) {
            const uint4* pl = (const uint4*)(Ss + (wm + mf * 16 + g) * HP + tg * 8);
            const uint4* ph = (const uint4*)(Ss + (wm + mf * 16 + g + 8) * HP + tg * 8);
            uint4 L0 = pl[0], L1 = pl[1], H0 = ph[0], H1 = ph[1];
#pragma unroll
            for (int kk = 0; kk < 4; kk++) {
                uint32_t a[4];
                a[0] = (kk == 0) ? L0.x : (kk == 1) ? L0.z : (kk == 2) ? L1.x : L1.z;
                a[1] = (kk == 0) ? H0.x : (kk == 1) ? H0.z : (kk == 2) ? H1.x : H1.z;
                a[2] = (kk == 0) ? L0.y : (kk == 1) ? L0.w : (kk == 2) ? L1.y : L1.w;
                a[3] = (kk == 0) ? H0.y : (kk == 1) ? H0.w : (kk == 2) ? H1.y : H1.w;
#pragma unroll
                for (int nf = 0; nf < 4; nf++) {
                    uint32_t b[2];
                    b[0] = (kk == 0) ? b4[nf][0].x : (kk == 1) ? b4[nf][0].z
                         : (kk == 2) ? b4[nf][1].x : b4[nf][1].z;
                    b[1] = (kk == 0) ? b4[nf][0].y : (kk == 1) ? b4[nf][0].w
                         : (kk == 2) ? b4[nf][1].y : b4[nf][1].w;
                    mma16(acc[mf][nf], a, b);
                }
            }
        }
        __syncthreads();
    }

#pragma unroll
    for (int mf = 0; mf < 4; mf++)
#pragma unroll
        for (int nf = 0; nf < 4; nf++) {
            int r0 = bm + wm + mf * 16 + g;
            int c0 = bn + wn + nf * 8 + tg * 2;
            float b0 = bias[c0], b1 = bias[c0 + 1];
            float v00 = acc[mf][nf][0] + b0, v01 = acc[mf][nf][1] + b1;
            float v10 = acc[mf][nf][2] + b0, v11 = acc[mf][nf][3] + b1;
            if (EPI == 0) {
                float* C = (float*)Cv;
                *(float2*)(C + (size_t)r0 * N + c0)       = make_float2(v00, v01);
                *(float2*)(C + (size_t)(r0 + 8) * N + c0) = make_float2(v10, v11);
            } else if (EPI == 1 || EPI == 3) {
                if (EPI == 3) { v00 *= QSCALE; v01 *= QSCALE; v10 *= QSCALE; v11 *= QSCALE; }
                __half* C = (__half*)Cv;
                int ja = (c0 & ~63) + j16h(c0 & 63);
                *(__half2*)(C + (size_t)r0 * N + ja) = __floats2half2_rn(v00, v01);
                *(__half2*)(C + (size_t)(r0 + 8) * N + ja) = __floats2half2_rn(v10, v11);
            } else {
                __half* C = (__half*)Cv;
                int ra = (r0 & ~63) + j16h(r0 & 63);
                int rb = (r0 & ~63) + j16h((r0 + 8) & 63);
                C[(size_t)c0 * ROWS + ra]       = __float2half_rn(v00);
                C[(size_t)(c0 + 1) * ROWS + ra] = __float2half_rn(v01);
                C[(size_t)c0 * ROWS + rb]       = __float2half_rn(v10);
                C[(size_t)(c0 + 1) * ROWS + rb] = __float2half_rn(v11);
            }
        }
}

__global__ __launch_bounds__(256) void qkv_gemm(
    const float* __restrict__ bq, const float* __restrict__ bk, const float* __restrict__ bv)
{
    int bx = blockIdx.x, bm = blockIdx.y * 128;
    if (bx < 8)       gemm_body<3>(g_xt, g_wqt, bq, g_q,  1024, bm, bx * 128);
    else if (bx < 10) gemm_body<1>(g_xt, g_wkt, bk, g_k,  256,  bm, (bx - 8) * 128);
    else              gemm_body<2>(g_xt, g_wvt, bv, g_vt, 256,  bm, (bx - 10) * 128);
}

__global__ __launch_bounds__(256) void o_gemm(const float* __restrict__ bo, float* __restrict__ out)
{
    gemm_body<0>(g_o, g_wot, bo, out, 1024, blockIdx.y * 128, blockIdx.x * 128);
}

// ============================================================
// fp16 flash attention v3: per-pair rotation + f16x2 exponent.
// Q-tile 128, 128 threads (4 warps x 32 q-rows), KV-tile 64,
// cp.async double buffer (36KB), 2 blocks/SM.
//   QK(jp+1) -> softmax(jp) [ex2.f16x2: half the MUFU ops] -> PV(jp)
// grid (SEQ/128, NH, BATCH).
// ============================================================
#define ASTGH (128 * HP)

__device__ __forceinline__ void cp_stage_attn(uint32_t sb, const __half* Kp, const __half* Vp, int tid) {
#pragma unroll
    for (int t = 0; t < 4; t++) {
        int cid = tid + t * 128; int row = cid >> 3, ch = cid & 7;
        cpa16(sb + (uint32_t)(row * HP + ch * 4) * 4, Kp + (size_t)row * 256 + ch * 8);
    }
#pragma unroll
    for (int t = 0; t < 4; t++) {
        int cid = tid + t * 128; int row = cid >> 3, ch = cid & 7;
        cpa16(sb + (uint32_t)((64 + row) * HP + ch * 4) * 4, Vp + (size_t)row * ROWS + ch * 8);
    }
    CP_COMMIT;
}

// QK for one nf-pair (tokens 16*jp..16*jp+15) into score buffer sbuf[2][2][4]
__device__ __forceinline__ void qk_pair(
    const uint32_t* Ks, int jp, int g, int tg,
    const uint32_t aQ[2][4][4], float sbuf[2][2][4])
{
    const uint4* kp0 = (const uint4*)(Ks + ((2 * jp) * 8 + g) * HP + tg * 8);
    const uint4* kp1 = (const uint4*)(Ks + ((2 * jp + 1) * 8 + g) * HP + tg * 8);
    uint4 P00 = kp0[0], P01 = kp0[1];
    uint4 P10 = kp1[0], P11 = kp1[1];
#pragma unroll
    for (int mf = 0; mf < 2; mf++)
#pragma unroll
        for (int nl = 0; nl < 2; nl++)
#pragma unroll
            for (int q = 0; q < 4; q++) sbuf[mf][nl][q] = 0.f;
#pragma unroll
    for (int kk = 0; kk < 4; kk++) {
        uint32_t b0[2], b1[2];
        b0[0] = (kk == 0) ? P00.x : (kk == 1) ? P00.z : (kk == 2) ? P01.x : P01.z;
        b0[1] = (kk == 0) ? P00.y : (kk == 1) ? P00.w : (kk == 2) ? P01.y : P01.w;
        b1[0] = (kk == 0) ? P10.x : (kk == 1) ? P10.z : (kk == 2) ? P11.x : P11.z;
        b1[1] = (kk == 0) ? P10.y : (kk == 1) ? P10.w : (kk == 2) ? P11.y : P11.w;
        mma16(sbuf[0][0], aQ[0][kk], b0);
        mma16(sbuf[1][0], aQ[1][kk], b0);
        mma16(sbuf[0][1], aQ[0][kk], b1);
        mma16(sbuf[1][1], aQ[1][kk], b1);
    }
}

__global__ __launch_bounds__(128, 2) void flash_attn()
{
    extern __shared__ uint32_t sm[];
    const int qt = blockIdx.x, h = blockIdx.y, b = blockIdx.z;
    const int kvh = h >> 2;
    const int tid = threadIdx.x, lane = tid & 31, w = tid >> 5;
    const int g = lane >> 2, tg = lane & 3;
    const int q0 = w * 32;
    uint32_t sbase = (uint32_t)__cvta_generic_to_shared(sm);

    // Q fragments: aQ[mf][kk][4]
    uint32_t aQ[2][4][4];
#pragma unroll
    for (int mf = 0; mf < 2; mf++) {
        int rowl = b * SEQ + qt * 128 + q0 + mf * 16 + g;
        const uint4* qlo = (const uint4*)(g_q + (size_t)rowl * 1024 + h * 64);
        const uint4* qhi = (const uint4*)(g_q + (size_t)(rowl + 8) * 1024 + h * 64);
        uint4 L0 = qlo[tg * 2], L1 = qlo[tg * 2 + 1];
        uint4 H0 = qhi[tg * 2], H1 = qhi[tg * 2 + 1];
        aQ[mf][0][0] = L0.x; aQ[mf][0][1] = H0.x; aQ[mf][0][2] = L0.y; aQ[mf][0][3] = H0.y;
        aQ[mf][1][0] = L0.z; aQ[mf][1][1] = H0.z; aQ[mf][1][2] = L0.w; aQ[mf][1][3] = H0.w;
        aQ[mf][2][0] = L1.x; aQ[mf][2][1] = H1.x; aQ[mf][2][2] = L1.y; aQ[mf][2][3] = H1.y;
        aQ[mf][3][0] = L1.z; aQ[mf][3][1] = H1.z; aQ[mf][3][2] = L1.w; aQ[mf][3][3] = H1.w;
    }

    float accO[2][8][4];
#pragma unroll
    for (int mf = 0; mf < 2; mf++)
#pragma unroll
        for (int i = 0; i < 8; i++)
#pragma unroll
            for (int j = 0; j < 4; j++) accO[mf][i][j] = 0.f;
    float lsum[2][2] = {{0.f, 0.f}, {0.f, 0.f}};

    const __half* Kbase = g_k + (size_t)(b * SEQ) * 256 + kvh * 64;
    const __half* Vbase = g_vt + (size_t)(kvh * 64) * ROWS + (size_t)b * SEQ;

    cp_stage_attn(sbase, Kbase, Vbase, tid);
    for (int kt = 0; kt < SEQ / 64; kt++) {
        if (kt < SEQ / 64 - 1) {
            cp_stage_attn(sbase + (uint32_t)(((kt + 1) & 1) * ASTGH * 4),
                          Kbase + (size_t)(kt + 1) * 64 * 256, Vbase + (kt + 1) * 64, tid);
            CP_WAIT1;
        } else {
            CP_WAIT0;
        }
        __syncthreads();
        const uint32_t* Ks = sm + (kt & 1) * ASTGH;
        const uint32_t* Vs = Ks + 64 * HP;

        float s[2][2][2][4];   // [buf][mf][nl][4]
        qk_pair(Ks, 0, g, tg, aQ, s[0]);

#pragma unroll
        for (int jp = 0; jp < 4; jp++) {
            const int cur = jp & 1, nxt = cur ^ 1;
            // fill tensor queue with next pair's QK before softmax
            if (jp < 3) qk_pair(Ks, jp + 1, g, tg, aQ, s[nxt]);

            // softmax(jp): pack s' pairs to fp16, single f16x2 exponent,
            // lsum from the exact fp16 P values (matches mma operands)
            uint32_t aP[2][4];
#pragma unroll
            for (int mf = 0; mf < 2; mf++) {
                uint32_t h0 = packh2(s[cur][mf][0][0], s[cur][mf][0][1]);  // row g,  nl0
                uint32_t h1 = packh2(s[cur][mf][0][2], s[cur][mf][0][3]);  // row g+8,nl0
                uint32_t h2 = packh2(s[cur][mf][1][0], s[cur][mf][1][1]);  // row g,  nl1
                uint32_t h3 = packh2(s[cur][mf][1][2], s[cur][mf][1][3]);  // row g+8,nl1
                uint32_t p0 = ex2h2(h0), p1 = ex2h2(h1), p2 = ex2h2(h2), p3 = ex2h2(h3);
                aP[mf][0] = p0; aP[mf][1] = p1; aP[mf][2] = p2; aP[mf][3] = p3;
                float2 f0 = __half22float2(*reinterpret_cast<__half2*>(&p0));
                float2 f1 = __half22float2(*reinterpret_cast<__half2*>(&p1));
                float2 f2 = __half22float2(*reinterpret_cast<__half2*>(&p2));
                float2 f3 = __half22float2(*reinterpret_cast<__half2*>(&p3));
                lsum[mf][0] += (f0.x + f0.y) + (f2.x + f2.y);
                lsum[mf][1] += (f1.x + f1.y) + (f3.x + f3.y);
            }

            // PV(jp): 16 independent mma
#pragma unroll
            for (int nfo = 0; nfo < 8; nfo++) {
                const uint2* vp = (const uint2*)(Vs + (nfo * 8 + g) * HP + tg * 8 + jp * 2);
                uint2 V = *vp;
                uint32_t bb[2] = {V.x, V.y};
                mma16(accO[0][nfo], aP[0], bb);
                mma16(accO[1][nfo], aP[1], bb);
            }
        }
        __syncthreads();
    }

    // epilogue: quad-reduce row sums, normalize, write permuted fp16 into g_o
#pragma unroll
    for (int mf = 0; mf < 2; mf++) {
        float l0 = lsum[mf][0], l1 = lsum[mf][1];
        l0 += __shfl_xor_sync(0xffffffffu, l0, 1);
        l0 += __shfl_xor_sync(0xffffffffu, l0, 2);
        l1 += __shfl_xor_sync(0xffffffffu, l1, 1);
        l1 += __shfl_xor_sync(0xffffffffu, l1, 2);
        float inv0 = 1.f / l0, inv1 = 1.f / l1;
        int rbase = b * SEQ + qt * 128 + q0 + mf * 16 + g;
        __half* Op = g_o + (size_t)rbase * 1024 + h * 64;
#pragma unroll
        for (int nfo = 0; nfo < 8; nfo++) {
            int f0 = nfo * 8 + tg * 2;
            int ja = j16h(f0);
            *(__half2*)(Op + ja) =
                __floats2half2_rn(accO[mf][nfo][0] * inv0, accO[mf][nfo][1] * inv0);
            *(__half2*)(Op + (size_t)8 * 1024 + ja) =
                __floats2half2_rn(accO[mf][nfo][2] * inv1, accO[mf][nfo][3] * inv1);
        }
    }
}

// ============================================================
extern "C" void kernel_launch(void* const* d_in, const int* in_sizes, int n_in,
                              void* d_out, int out_size)
{
    const float* x  = (const float*)d_in[0];
    const float* Wq = (const float*)d_in[1];
    const float* bq = (const float*)d_in[2];
    const float* Wk = (const float*)d_in[3];
    const float* bk = (const float*)d_in[4];
    const float* Wv = (const float*)d_in[5];
    const float* bv = (const float*)d_in[6];
    const float* Wo = (const float*)d_in[7];
    const float* bo = (const float*)d_in[8];
    float* out = (float*)d_out;

    int gsmem = 2 * GSTGH * 4;   // 73728
    cudaFuncSetAttribute(qkv_gemm, cudaFuncAttributeMaxDynamicSharedMemorySize, gsmem);
    cudaFuncSetAttribute(o_gemm,   cudaFuncAttributeMaxDynamicSharedMemorySize, gsmem);
    int asmem = 2 * ASTGH * 4;   // 36864
    cudaFuncSetAttribute(flash_attn, cudaFuncAttributeMaxDynamicSharedMemorySize, asmem);

    prep_act<<<ROWS * 1024 / 1024, 256>>>(x);
    prep_w<<<dim3(10, 1024), 256>>>(Wq, Wk, Wv, Wo);

    qkv_gemm<<<dim3(12, ROWS / 128), 256, gsmem>>>(bq, bk, bv);
    flash_attn<<<dim3(SEQ / 128, NH, BATCH), 128, asmem>>>();
    o_gemm<<<dim3(8, ROWS / 128), 256, gsmem>>>(bo, out);
}

// round 16
// speedup vs baseline: 1.0341x; 1.0341x over previous
#include <cuda_runtime.h>
#include <cuda_fp16.h>
#include <cstdint>

#define D_MODEL 1024
#define NH 16
#define DK 64
#define BATCH 2
#define SEQ 2048
#define ROWS (BATCH*SEQ)

// Q prescale: (1/sqrt(64)) * log2(e)
#define QSCALE 0.18033688011112042f

// ---- scratch (no allocations allowed) ----
__device__ __align__(16) __half g_xt [ROWS * 1024];
__device__ __align__(16) __half g_wqt[1024 * 1024];
__device__ __align__(16) __half g_wkt[256  * 1024];
__device__ __align__(16) __half g_wvt[256  * 1024];
__device__ __align__(16) __half g_wot[1024 * 1024];
__device__ __align__(16) __half g_q  [ROWS * 1024];
__device__ __align__(16) __half g_k  [ROWS * 256];
__device__ __align__(16) __half g_vt [256  * ROWS];
__device__ __align__(16) __half g_o  [ROWS * 1024];

__device__ __forceinline__ float ex2(float x) {
    float y;
    asm("ex2.approx.ftz.f32 %0, %1;" : "=f"(y) : "f"(x));
    return y;
}

// fp16 pair permutation within a 64-feature block:
// feature k = 16*kk + 8*h2 + 2*tg + s  <->  stored pos j = 16*tg + 4*kk + 2*h2 + s
__device__ __forceinline__ int j16h(int k) {
    return ((k >> 1) & 3) * 16 + (k >> 4) * 4 + ((k >> 3) & 1) * 2 + (k & 1);
}
__device__ __forceinline__ int sig64h(int j) {
    return ((j >> 2) & 3) * 16 + ((j >> 1) & 1) * 8 + (j >> 4) * 2 + (j & 1);
}

__device__ __forceinline__ uint32_t packh2(float lo, float hi) {
    __half2 h = __floats2half2_rn(lo, hi);
    return *reinterpret_cast<uint32_t*>(&h);
}

__device__ __forceinline__ void mma16(float* c, const uint32_t* a, const uint32_t* b) {
    asm volatile(
        "mma.sync.aligned.m16n8k16.row.col.f32.f16.f16.f32 "
        "{%0,%1,%2,%3},{%4,%5,%6,%7},{%8,%9},{%0,%1,%2,%3};"
        : "+f"(c[0]), "+f"(c[1]), "+f"(c[2]), "+f"(c[3])
        : "r"(a[0]), "r"(a[1]), "r"(a[2]), "r"(a[3]), "r"(b[0]), "r"(b[1]));
}

__device__ __forceinline__ void cpa16(uint32_t dst, const void* src) {
    asm volatile("cp.async.cg.shared.global [%0], [%1], 16;\n" :: "r"(dst), "l"(src) : "memory");
}
#define CP_COMMIT asm volatile("cp.async.commit_group;\n" ::: "memory")
#define CP_WAIT1  asm volatile("cp.async.wait_group 1;\n" ::: "memory")
#define CP_WAIT0  asm volatile("cp.async.wait_group 0;\n" ::: "memory")

#define HP 36   // smem pitch in words for a 64-half (128B) row

// ============================================================
// Prepass kernels
// ============================================================
__global__ __launch_bounds__(256) void prep_act(const float* __restrict__ in) {
    int i4 = (blockIdx.x * 256 + threadIdx.x) * 4;
    int base = i4 & ~63;
    float f0 = in[base + sig64h((i4 + 0) & 63)];
    float f1 = in[base + sig64h((i4 + 1) & 63)];
    float f2 = in[base + sig64h((i4 + 2) & 63)];
    float f3 = in[base + sig64h((i4 + 3) & 63)];
    __half2* o2 = (__half2*)(g_xt + i4);
    o2[0] = __floats2half2_rn(f0, f1);
    o2[1] = __floats2half2_rn(f2, f3);
}

__global__ __launch_bounds__(256) void prep_w(
    const float* __restrict__ Wq, const float* __restrict__ Wk,
    const float* __restrict__ Wv, const float* __restrict__ Wo)
{
    int col = blockIdx.x * 256 + threadIdx.x;
    int kp = blockIdx.y;
    int k = (kp & ~63) + sig64h(kp & 63);
    const float* W; __half* Wt; int N, n;
    if (col < 1024)      { W = Wq; Wt = g_wqt; N = 1024; n = col; }
    else if (col < 1280) { W = Wk; Wt = g_wkt; N = 256;  n = col - 1024; }
    else if (col < 1536) { W = Wv; Wt = g_wvt; N = 256;  n = col - 1280; }
    else                 { W = Wo; Wt = g_wot; N = 1024; n = col - 1536; }
    Wt[(size_t)n * 1024 + kp] = __float2half_rn(W[(size_t)k * N + n]);
}

// ============================================================
// fp16 GEMM v2: C[M,N] = A[M,1024] @ Bt[N,1024]^T + bias
// block 128x128, 4 warps (2x2) of 64x64, BK=64 (4 x k16 mma),
// cp.async double buffer (72KB), 2 blocks/SM.
// ratio: 128 mma per 32 LDS.128 per warp per kt.
// ============================================================
#define GSTGH (256 * HP)

__device__ __forceinline__ void cp_stage_gemm(uint32_t sb, const __half* Ap, const __half* Bp, int tid) {
#pragma unroll
    for (int t = 0; t < 8; t++) {
        int cid = tid + t * 128; int row = cid >> 3, ch = cid & 7;
        cpa16(sb + (uint32_t)(row * HP + ch * 4) * 4, Ap + (size_t)row * 1024 + ch * 8);
    }
#pragma unroll
    for (int t = 0; t < 8; t++) {
        int cid = tid + t * 128; int row = cid >> 3, ch = cid & 7;
        cpa16(sb + (uint32_t)((128 + row) * HP + ch * 4) * 4, Bp + (size_t)row * 1024 + ch * 8);
    }
    CP_COMMIT;
}

template<int EPI>
__device__ __forceinline__ void gemm_body(
    const __half* __restrict__ A, const __half* __restrict__ Bt,
    const float* __restrict__ bias, void* __restrict__ Cv,
    int N, int bm, int bn)
{
    extern __shared__ uint32_t smg[];
    const int tid = threadIdx.x, lane = tid & 31, w = tid >> 5;
    const int g = lane >> 2, tg = lane & 3;
    const int wm = (w >> 1) * 64, wn = (w & 1) * 64;
    uint32_t sbase = (uint32_t)__cvta_generic_to_shared(smg);
    const __half* Ab = A + (size_t)bm * 1024;
    const __half* Bb = Bt + (size_t)bn * 1024;

    float acc[4][8][4];
#pragma unroll
    for (int i = 0; i < 4; i++)
#pragma unroll
        for (int j = 0; j < 8; j++)
#pragma unroll
            for (int q = 0; q < 4; q++) acc[i][j][q] = 0.f;

    cp_stage_gemm(sbase, Ab, Bb, tid);
    for (int kt = 0; kt < 16; kt++) {
        if (kt < 15) {
            cp_stage_gemm(sbase + (uint32_t)(((kt + 1) & 1) * GSTGH * 4),
                          Ab + (kt + 1) * 64, Bb + (kt + 1) * 64, tid);
            CP_WAIT1;
        } else {
            CP_WAIT0;
        }
        __syncthreads();
        const uint32_t* Ss = smg + (kt & 1) * GSTGH;

        // B fragments: 8 nf rows x 8 words (64 N-columns)
        uint4 b4[8][2];
#pragma unroll
        for (int nf = 0; nf < 8; nf++) {
            const uint4* p = (const uint4*)(Ss + (128 + wn + nf * 8 + g) * HP + tg * 8);
            b4[nf][0] = p[0]; b4[nf][1] = p[1];
        }
#pragma unroll
        for (int mf = 0; mf < 4; mf++) {
            const uint4* pl = (const uint4*)(Ss + (wm + mf * 16 + g) * HP + tg * 8);
            const uint4* ph = (const uint4*)(Ss + (wm + mf * 16 + g + 8) * HP + tg * 8);
            uint4 L0 = pl[0], L1 = pl[1], H0 = ph[0], H1 = ph[1];
#pragma unroll
            for (int kk = 0; kk < 4; kk++) {
                uint32_t a[4];
                a[0] = (kk == 0) ? L0.x : (kk == 1) ? L0.z : (kk == 2) ? L1.x : L1.z;
                a[1] = (kk == 0) ? H0.x : (kk == 1) ? H0.z : (kk == 2) ? H1.x : H1.z;
                a[2] = (kk == 0) ? L0.y : (kk == 1) ? L0.w : (kk == 2) ? L1.y : L1.w;
                a[3] = (kk == 0) ? H0.y : (kk == 1) ? H0.w : (kk == 2) ? H1.y : H1.w;
#pragma unroll
                for (int nf = 0; nf < 8; nf++) {
                    uint32_t b[2];
                    b[0] = (kk == 0) ? b4[nf][0].x : (kk == 1) ? b4[nf][0].z
                         : (kk == 2) ? b4[nf][1].x : b4[nf][1].z;
                    b[1] = (kk == 0) ? b4[nf][0].y : (kk == 1) ? b4[nf][0].w
                         : (kk == 2) ? b4[nf][1].y : b4[nf][1].w;
                    mma16(acc[mf][nf], a, b);
                }
            }
        }
        __syncthreads();
    }

#pragma unroll
    for (int mf = 0; mf < 4; mf++)
#pragma unroll
        for (int nf = 0; nf < 8; nf++) {
            int r0 = bm + wm + mf * 16 + g;
            int c0 = bn + wn + nf * 8 + tg * 2;
            float b0 = bias[c0], b1 = bias[c0 + 1];
            float v00 = acc[mf][nf][0] + b0, v01 = acc[mf][nf][1] + b1;
            float v10 = acc[mf][nf][2] + b0, v11 = acc[mf][nf][3] + b1;
            if (EPI == 0) {
                float* C = (float*)Cv;
                *(float2*)(C + (size_t)r0 * N + c0)       = make_float2(v00, v01);
                *(float2*)(C + (size_t)(r0 + 8) * N + c0) = make_float2(v10, v11);
            } else if (EPI == 1 || EPI == 3) {
                if (EPI == 3) { v00 *= QSCALE; v01 *= QSCALE; v10 *= QSCALE; v11 *= QSCALE; }
                __half* C = (__half*)Cv;
                int ja = (c0 & ~63) + j16h(c0 & 63);
                *(__half2*)(C + (size_t)r0 * N + ja) = __floats2half2_rn(v00, v01);
                *(__half2*)(C + (size_t)(r0 + 8) * N + ja) = __floats2half2_rn(v10, v11);
            } else {
                __half* C = (__half*)Cv;
                int ra = (r0 & ~63) + j16h(r0 & 63);
                int rb = (r0 & ~63) + j16h((r0 + 8) & 63);
                C[(size_t)c0 * ROWS + ra]       = __float2half_rn(v00);
                C[(size_t)(c0 + 1) * ROWS + ra] = __float2half_rn(v01);
                C[(size_t)c0 * ROWS + rb]       = __float2half_rn(v10);
                C[(size_t)(c0 + 1) * ROWS + rb] = __float2half_rn(v11);
            }
        }
}

__global__ __launch_bounds__(128, 2) void qkv_gemm(
    const float* __restrict__ bq, const float* __restrict__ bk, const float* __restrict__ bv)
{
    int bx = blockIdx.x, bm = blockIdx.y * 128;
    if (bx < 8)       gemm_body<3>(g_xt, g_wqt, bq, g_q,  1024, bm, bx * 128);
    else if (bx < 10) gemm_body<1>(g_xt, g_wkt, bk, g_k,  256,  bm, (bx - 8) * 128);
    else              gemm_body<2>(g_xt, g_wvt, bv, g_vt, 256,  bm, (bx - 10) * 128);
}

__global__ __launch_bounds__(128, 2) void o_gemm(const float* __restrict__ bo, float* __restrict__ out)
{
    gemm_body<0>(g_o, g_wot, bo, out, 1024, blockIdx.y * 128, blockIdx.x * 128);
}

// ============================================================
// fp16 flash attention (R14 best, reverted): per-pair rotation.
// Q-tile 128, 128 threads (4 warps x 32 q-rows), KV-tile 64,
// cp.async double buffer (36KB), 2 blocks/SM.
//   QK(jp+1) -> softmax(jp) [fp32 ex2] -> PV(jp)
// grid (SEQ/128, NH, BATCH).
// ============================================================
#define ASTGH (128 * HP)

__device__ __forceinline__ void cp_stage_attn(uint32_t sb, const __half* Kp, const __half* Vp, int tid) {
#pragma unroll
    for (int t = 0; t < 4; t++) {
        int cid = tid + t * 128; int row = cid >> 3, ch = cid & 7;
        cpa16(sb + (uint32_t)(row * HP + ch * 4) * 4, Kp + (size_t)row * 256 + ch * 8);
    }
#pragma unroll
    for (int t = 0; t < 4; t++) {
        int cid = tid + t * 128; int row = cid >> 3, ch = cid & 7;
        cpa16(sb + (uint32_t)((64 + row) * HP + ch * 4) * 4, Vp + (size_t)row * ROWS + ch * 8);
    }
    CP_COMMIT;
}

__device__ __forceinline__ void qk_pair(
    const uint32_t* Ks, int jp, int g, int tg,
    const uint32_t aQ[2][4][4], float sbuf[2][2][4])
{
    const uint4* kp0 = (const uint4*)(Ks + ((2 * jp) * 8 + g) * HP + tg * 8);
    const uint4* kp1 = (const uint4*)(Ks + ((2 * jp + 1) * 8 + g) * HP + tg * 8);
    uint4 P00 = kp0[0], P01 = kp0[1];
    uint4 P10 = kp1[0], P11 = kp1[1];
#pragma unroll
    for (int mf = 0; mf < 2; mf++)
#pragma unroll
        for (int nl = 0; nl < 2; nl++)
#pragma unroll
            for (int q = 0; q < 4; q++) sbuf[mf][nl][q] = 0.f;
#pragma unroll
    for (int kk = 0; kk < 4; kk++) {
        uint32_t b0[2], b1[2];
        b0[0] = (kk == 0) ? P00.x : (kk == 1) ? P00.z : (kk == 2) ? P01.x : P01.z;
        b0[1] = (kk == 0) ? P00.y : (kk == 1) ? P00.w : (kk == 2) ? P01.y : P01.w;
        b1[0] = (kk == 0) ? P10.x : (kk == 1) ? P10.z : (kk == 2) ? P11.x : P11.z;
        b1[1] = (kk == 0) ? P10.y : (kk == 1) ? P10.w : (kk == 2) ? P11.y : P11.w;
        mma16(sbuf[0][0], aQ[0][kk], b0);
        mma16(sbuf[1][0], aQ[1][kk], b0);
        mma16(sbuf[0][1], aQ[0][kk], b1);
        mma16(sbuf[1][1], aQ[1][kk], b1);
    }
}

__global__ __launch_bounds__(128, 2) void flash_attn()
{
    extern __shared__ uint32_t sm[];
    const int qt = blockIdx.x, h = blockIdx.y, b = blockIdx.z;
    const int kvh = h >> 2;
    const int tid = threadIdx.x, lane = tid & 31, w = tid >> 5;
    const int g = lane >> 2, tg = lane & 3;
    const int q0 = w * 32;
    uint32_t sbase = (uint32_t)__cvta_generic_to_shared(sm);

    uint32_t aQ[2][4][4];
#pragma unroll
    for (int mf = 0; mf < 2; mf++) {
        int rowl = b * SEQ + qt * 128 + q0 + mf * 16 + g;
        const uint4* qlo = (const uint4*)(g_q + (size_t)rowl * 1024 + h * 64);
        const uint4* qhi = (const uint4*)(g_q + (size_t)(rowl + 8) * 1024 + h * 64);
        uint4 L0 = qlo[tg * 2], L1 = qlo[tg * 2 + 1];
        uint4 H0 = qhi[tg * 2], H1 = qhi[tg * 2 + 1];
        aQ[mf][0][0] = L0.x; aQ[mf][0][1] = H0.x; aQ[mf][0][2] = L0.y; aQ[mf][0][3] = H0.y;
        aQ[mf][1][0] = L0.z; aQ[mf][1][1] = H0.z; aQ[mf][1][2] = L0.w; aQ[mf][1][3] = H0.w;
        aQ[mf][2][0] = L1.x; aQ[mf][2][1] = H1.x; aQ[mf][2][2] = L1.y; aQ[mf][2][3] = H1.y;
        aQ[mf][3][0] = L1.z; aQ[mf][3][1] = H1.z; aQ[mf][3][2] = L1.w; aQ[mf][3][3] = H1.w;
    }

    float accO[2][8][4];
#pragma unroll
    for (int mf = 0; mf < 2; mf++)
#pragma unroll
        for (int i = 0; i < 8; i++)
#pragma unroll
            for (int j = 0; j < 4; j++) accO[mf][i][j] = 0.f;
    float lsum[2][2] = {{0.f, 0.f}, {0.f, 0.f}};

    const __half* Kbase = g_k + (size_t)(b * SEQ) * 256 + kvh * 64;
    const __half* Vbase = g_vt + (size_t)(kvh * 64) * ROWS + (size_t)b * SEQ;

    cp_stage_attn(sbase, Kbase, Vbase, tid);
    for (int kt = 0; kt < SEQ / 64; kt++) {
        if (kt < SEQ / 64 - 1) {
            cp_stage_attn(sbase + (uint32_t)(((kt + 1) & 1) * ASTGH * 4),
                          Kbase + (size_t)(kt + 1) * 64 * 256, Vbase + (kt + 1) * 64, tid);
            CP_WAIT1;
        } else {
            CP_WAIT0;
        }
        __syncthreads();
        const uint32_t* Ks = sm + (kt & 1) * ASTGH;
        const uint32_t* Vs = Ks + 64 * HP;

        float s[2][2][2][4];
        qk_pair(Ks, 0, g, tg, aQ, s[0]);

#pragma unroll
        for (int jp = 0; jp < 4; jp++) {
            const int cur = jp & 1, nxt = cur ^ 1;
            if (jp < 3) qk_pair(Ks, jp + 1, g, tg, aQ, s[nxt]);

            uint32_t aP[2][4];
#pragma unroll
            for (int mf = 0; mf < 2; mf++) {
                float pa0 = ex2(s[cur][mf][0][0]);
                float pa1 = ex2(s[cur][mf][0][1]);
                float pa2 = ex2(s[cur][mf][0][2]);
                float pa3 = ex2(s[cur][mf][0][3]);
                float pb0 = ex2(s[cur][mf][1][0]);
                float pb1 = ex2(s[cur][mf][1][1]);
                float pb2 = ex2(s[cur][mf][1][2]);
                float pb3 = ex2(s[cur][mf][1][3]);
                lsum[mf][0] += pa0 + pa1 + pb0 + pb1;
                lsum[mf][1] += pa2 + pa3 + pb2 + pb3;
                aP[mf][0] = packh2(pa0, pa1);
                aP[mf][1] = packh2(pa2, pa3);
                aP[mf][2] = packh2(pb0, pb1);
                aP[mf][3] = packh2(pb2, pb3);
            }

#pragma unroll
            for (int nfo = 0; nfo < 8; nfo++) {
                const uint2* vp = (const uint2*)(Vs + (nfo * 8 + g) * HP + tg * 8 + jp * 2);
                uint2 V = *vp;
                uint32_t bb[2] = {V.x, V.y};
                mma16(accO[0][nfo], aP[0], bb);
                mma16(accO[1][nfo], aP[1], bb);
            }
        }
        __syncthreads();
    }

#pragma unroll
    for (int mf = 0; mf < 2; mf++) {
        float l0 = lsum[mf][0], l1 = lsum[mf][1];
        l0 += __shfl_xor_sync(0xffffffffu, l0, 1);
        l0 += __shfl_xor_sync(0xffffffffu, l0, 2);
        l1 += __shfl_xor_sync(0xffffffffu, l1, 1);
        l1 += __shfl_xor_sync(0xffffffffu, l1, 2);
        float inv0 = 1.f / l0, inv1 = 1.f / l1;
        int rbase = b * SEQ + qt * 128 + q0 + mf * 16 + g;
        __half* Op = g_o + (size_t)rbase * 1024 + h * 64;
#pragma unroll
        for (int nfo = 0; nfo < 8; nfo++) {
            int f0 = nfo * 8 + tg * 2;
            int ja = j16h(f0);
            *(__half2*)(Op + ja) =
                __floats2half2_rn(accO[mf][nfo][0] * inv0, accO[mf][nfo][1] * inv0);
            *(__half2*)(Op + (size_t)8 * 1024 + ja) =
                __floats2half2_rn(accO[mf][nfo][2] * inv1, accO[mf][nfo][3] * inv1);
        }
    }
}

// ============================================================
extern "C" void kernel_launch(void* const* d_in, const int* in_sizes, int n_in,
                              void* d_out, int out_size)
{
    const float* x  = (const float*)d_in[0];
    const float* Wq = (const float*)d_in[1];
    const float* bq = (const float*)d_in[2];
    const float* Wk = (const float*)d_in[3];
    const float* bk = (const float*)d_in[4];
    const float* Wv = (const float*)d_in[5];
    const float* bv = (const float*)d_in[6];
    const float* Wo = (const float*)d_in[7];
    const float* bo = (const float*)d_in[8];
    float* out = (float*)d_out;

    int gsmem = 2 * GSTGH * 4;   // 73728
    cudaFuncSetAttribute(qkv_gemm, cudaFuncAttributeMaxDynamicSharedMemorySize, gsmem);
    cudaFuncSetAttribute(o_gemm,   cudaFuncAttributeMaxDynamicSharedMemorySize, gsmem);
    int asmem = 2 * ASTGH * 4;   // 36864
    cudaFuncSetAttribute(flash_attn, cudaFuncAttributeMaxDynamicSharedMemorySize, asmem);

    prep_act<<<ROWS * 1024 / 1024, 256>>>(x);
    prep_w<<<dim3(10, 1024), 256>>>(Wq, Wk, Wv, Wo);

    qkv_gemm<<<dim3(12, ROWS / 128), 128, gsmem>>>(bq, bk, bv);
    flash_attn<<<dim3(SEQ / 128, NH, BATCH), 128, asmem>>>();
    o_gemm<<<dim3(8, ROWS / 128), 128, gsmem>>>(bo, out);
}